// round 16
// baseline (speedup 1.0000x reference)
#include <cuda_runtime.h>
#include <cuda_bf16.h>
#include <mma.h>
#include <math.h>
#include <stdint.h>

using namespace nvcuda;

// ---------------- problem constants ----------------
#define B   32
#define LP  2048
#define LD  512
#define DP  1280
#define DD  768
#define GP  (LP/8)      // 256
#define GD  (LD/8)      // 64
#define HID 512
#define NH  8
#define HD  64
#define INFV 1e6f
#define EPS 1e-5f

// ---------------- device scratch (static; no allocs) ----------------
__device__ __nv_bfloat16 d_pgEh[B*GP*DP], d_pgEl[B*GP*DP];
__device__ __nv_bfloat16 d_dgEh[B*GD*DD], d_dgEl[B*GD*DD];
__device__ __nv_bfloat16 d_pgh [B*GP*HID], d_pgl [B*GP*HID];
__device__ __nv_bfloat16 d_dgh [B*GD*HID], d_dgl [B*GD*HID];
__device__ __nv_bfloat16 d_wpt_h[HID*DP],  d_wpt_l[HID*DP];
__device__ __nv_bfloat16 d_wdt_h[HID*DD],  d_wdt_l[HID*DD];
__device__ __nv_bfloat16 d_wqp_t[2][3][HID*HID];
__device__ __nv_bfloat16 d_wqd_t[2][3][HID*HID];
__device__ float d_qkvp[3][B*GP*HID];
__device__ float d_qkvd[3][B*GD*HID];
__device__ float d_pe [B*GP*HID];
__device__ float d_de [B*GD*HID];
__device__ int   d_mp [B*GP];
__device__ int   d_md [B*GD];
__device__ float d_x  [B*1024];
__device__ float d_x1 [B*1024];
__device__ float d_x2 [B*512];
__device__ float d_x3 [B*256];
__device__ int   d_mask_layout;

// ---------------- small helpers ----------------
__device__ __forceinline__ void bsplit(float x, __nv_bfloat16& h, __nv_bfloat16& l) {
    h = __float2bfloat16(x);
    l = __float2bfloat16(x - __bfloat162float(h));
}
__device__ __forceinline__ void cpa16(uint32_t daddr, const void* g) {
    asm volatile("cp.async.cg.shared.global [%0], [%1], 16;" :: "r"(daddr), "l"(g));
}

// ---------------- mask layout detection (parallel; 256 threads x 16B) ----------------
__global__ void detect_mask_kernel(const unsigned char* __restrict__ m) {
    __shared__ int fu8, ff32;
    if (threadIdx.x == 0) { fu8 = 0; ff32 = 0; }
    __syncthreads();
    int u8 = 0, f32 = 0;
    const int base = threadIdx.x * 16;
    #pragma unroll
    for (int i = base; i < base + 16; i++) {
        unsigned char v = m[i];
        int r = i & 3;
        if (r != 0 && v != 0) { if (v == 1) u8 = 1; else f32 = 1; }
    }
    if (u8)  atomicOr(&fu8, 1);
    if (f32) atomicOr(&ff32, 1);
    __syncthreads();
    if (threadIdx.x == 0) d_mask_layout = fu8 ? 1 : (ff32 ? 2 : 0);
}
__device__ __forceinline__ int read_mask(const void* m, int idx, int layout) {
    if (layout == 0) return ((const int*)m)[idx] != 0;
    if (layout == 1) return ((const unsigned char*)m)[idx] != 0;
    return ((const float*)m)[idx] != 0.0f;
}

// ---------------- fused mask grouping (prot + drug in one launch) ----------------
__global__ void group_mask_all_kernel(const void* __restrict__ mP, const void* __restrict__ mD,
                                      int* __restrict__ mp, int* __restrict__ md) {
    int idx = blockIdx.x * blockDim.x + threadIdx.x;
    int layout = d_mask_layout;
    if (idx < B*GP) {
        int g = idx % GP, b = idx / GP;
        int any = 0;
        #pragma unroll
        for (int r = 0; r < 8; r++) any |= read_mask(mP, b*LP + g*8 + r, layout);
        mp[idx] = any;
    } else if (idx < B*GP + B*GD) {
        int j = idx - B*GP;
        int g = j % GD, b = j / GD;
        int any = 0;
        #pragma unroll
        for (int r = 0; r < 8; r++) any |= read_mask(mD, b*LD + g*8 + r, layout);
        md[j] = any;
    }
}

// ---------------- grouping: mean over 8 rows -> bf16 hi/lo split (HBM-roof, keep) ----------------
__global__ void group_embed_split_kernel(const float4* __restrict__ X,
                                         __nv_bfloat16* __restrict__ Yh,
                                         __nv_bfloat16* __restrict__ Yl,
                                         int L, int D4) {
    long idx = (long)blockIdx.x * blockDim.x + threadIdx.x;
    long total = (long)B * (L/8) * D4;
    if (idx >= total) return;
    int d   = (int)(idx % D4);
    long bg = idx / D4;
    int g  = (int)(bg % (L/8));
    int b  = (int)(bg / (L/8));
    const float4* p = X + ((long)b*L + (long)g*8) * D4 + d;
    float sx=0.f, sy=0.f, sz=0.f, sw=0.f;
    #pragma unroll
    for (int r = 0; r < 8; r++) {
        float4 v = p[(long)r*D4];
        sx += v.x; sy += v.y; sz += v.z; sw += v.w;
    }
    __nv_bfloat16 h0,l0,h1,l1,h2,l2,h3,l3;
    bsplit(sx*0.125f, h0, l0); bsplit(sy*0.125f, h1, l1);
    bsplit(sz*0.125f, h2, l2); bsplit(sw*0.125f, h3, l3);
    __nv_bfloat162* yh = (__nv_bfloat162*)Yh;
    __nv_bfloat162* yl = (__nv_bfloat162*)Yl;
    yh[idx*2+0] = __nv_bfloat162(h0, h1); yh[idx*2+1] = __nv_bfloat162(h2, h3);
    yl[idx*2+0] = __nv_bfloat162(l0, l1); yl[idx*2+1] = __nv_bfloat162(l2, l3);
}

// ---------------- smem-tiled weight transpose + bf16 split (8 jobs, one launch) ----------------
struct TSJob  { const float* W; __nv_bfloat16 *Th, *Tl; int K; };
struct TSJobs { TSJob j[8]; };
__global__ void transpose_all_kernel(TSJobs jobs) {
    TSJob jb = jobs.j[blockIdx.z];
    int k0 = blockIdx.x * 32, n0 = blockIdx.y * 32;
    if (k0 >= jb.K) return;
    __shared__ __nv_bfloat16 th[32][33], tl[32][33];
    int tx = threadIdx.x, ty = threadIdx.y;   // (32, 8)
    #pragma unroll
    for (int i = 0; i < 4; i++) {
        int kk = ty + i*8;
        float v = jb.W[(long)(k0 + kk) * HID + n0 + tx];   // coalesced (n fast)
        bsplit(v, th[kk][tx], tl[kk][tx]);
    }
    __syncthreads();
    #pragma unroll
    for (int i = 0; i < 4; i++) {
        int nn = ty + i*8;
        long o = (long)(n0 + nn) * jb.K + k0 + tx;          // coalesced (k fast)
        jb.Th[o] = th[tx][nn];
        jb.Tl[o] = tl[tx][nn];
    }
}

// ---------------- wmma GEMM: 128x64 tile, 3 CTAs/SM, cp.async double-buffered ----------------
// C[M,512] = A[M,K] @ T[512,K]^T ; compensated bf16: Ah*Bh + Al*Bh + Ah*Bl.
// 8 warps: wm 0..3 (32-row strips) x wn 0..1 (32-col strips); warp tile 32x32 (2x2 frags).
// smem/buffer 30KB -> 61KB double-buffered -> 3 CTAs/SM (was 80KB -> 2 CTAs, occ 22.6%).
// Grid of half-size CTAs also shrinks the wave-quantization tail seen at grid=320.
#define GT_PAD  40
#define GT_A    (128*GT_PAD)                 // 5120 elem per A operand
#define GT_B    (64*GT_PAD)                  // 2560 elem per B operand
#define GT_BUF  (2*GT_A + 2*GT_B)            // Ah|Al|Bh|Bl = 15360 elem
#define GT_SMEM (2*GT_BUF*2)                 // 61440 bytes
struct GJob {
    const __nv_bfloat16 *Ah, *Al;
    const __nv_bfloat16 *Wh0, *Wh1, *Wh2, *Wl0, *Wl1, *Wl2;
    float *C0, *C1, *C2;
    const float* bias;
    __nv_bfloat16 *Yh, *Yl;
    int K, tiles;
};
struct GJobs { GJob j[2]; };
__global__ __launch_bounds__(256, 3) void gemm_wmma_kernel(GJobs jobs) {
    extern __shared__ __nv_bfloat16 smem[];
    int yt = blockIdx.y;
    GJob jb = jobs.j[0];
    if (yt >= jb.tiles) { yt -= jb.tiles; jb = jobs.j[1]; }

    const __nv_bfloat16* Wh = (blockIdx.z == 0) ? jb.Wh0 : (blockIdx.z == 1) ? jb.Wh1 : jb.Wh2;
    const __nv_bfloat16* Wl = (blockIdx.z == 0) ? jb.Wl0 : (blockIdx.z == 1) ? jb.Wl1 : jb.Wl2;
    float* C                = (blockIdx.z == 0) ? jb.C0  : (blockIdx.z == 1) ? jb.C1  : jb.C2;
    const __nv_bfloat16* Ahi = jb.Ah;
    const __nv_bfloat16* Alo = jb.Al;
    const int K = jb.K;

    const int tid  = threadIdx.x;
    const int warp = tid >> 5;
    const int lane = tid & 31;
    const int wm   = warp & 3;
    const int wn   = warp >> 2;
    const int rowBase = yt * 128, nBase = blockIdx.x * 64;
    const int nCh = K >> 5;

    wmma::fragment<wmma::accumulator, 16, 16, 16, float> acc[2][2];
    #pragma unroll
    for (int mi = 0; mi < 2; mi++)
        #pragma unroll
        for (int ni = 0; ni < 2; ni++) wmma::fill_fragment(acc[mi][ni], 0.f);

    auto stage = [&](int ch, int buf) {
        const int k0 = ch << 5;
        __nv_bfloat16* s = smem + buf * GT_BUF;
        for (int u = tid; u < 512; u += 256) {
            int r = u >> 2, c8 = (u & 3) << 3;
            long ga = (long)(rowBase + r) * K + k0 + c8;
            uint32_t d0 = (uint32_t)__cvta_generic_to_shared(s + r*GT_PAD + c8);
            cpa16(d0,            Ahi + ga);
            cpa16(d0 + 2*GT_A,   Alo + ga);
            if (r < 64) {
                long gb = (long)(nBase + r) * K + k0 + c8;
                uint32_t d1 = (uint32_t)__cvta_generic_to_shared(s + 2*GT_A + r*GT_PAD + c8);
                cpa16(d1,          Wh + gb);
                cpa16(d1 + 2*GT_B, Wl + gb);
            }
        }
    };

    stage(0, 0);
    asm volatile("cp.async.commit_group;" ::: "memory");

    for (int ch = 0; ch < nCh; ch++) {
        const int buf = ch & 1;
        if (ch + 1 < nCh) {
            stage(ch + 1, 1 - buf);
            asm volatile("cp.async.commit_group;" ::: "memory");
            asm volatile("cp.async.wait_group 1;" ::: "memory");
        } else {
            asm volatile("cp.async.wait_group 0;" ::: "memory");
        }
        __syncthreads();

        const __nv_bfloat16* sAh = smem + buf*GT_BUF;
        const __nv_bfloat16* sAl = sAh + GT_A;
        const __nv_bfloat16* sBh = sAh + 2*GT_A;
        const __nv_bfloat16* sBl = sBh + GT_B;

        #pragma unroll
        for (int ks = 0; ks < 2; ks++) {
            wmma::fragment<wmma::matrix_a, 16, 16, 16, __nv_bfloat16, wmma::row_major> a_h[2], a_l[2];
            #pragma unroll
            for (int mi = 0; mi < 2; mi++) {
                int r = (wm*32 + mi*16) * GT_PAD + ks*16;
                wmma::load_matrix_sync(a_h[mi], sAh + r, GT_PAD);
                wmma::load_matrix_sync(a_l[mi], sAl + r, GT_PAD);
            }
            #pragma unroll
            for (int ni = 0; ni < 2; ni++) {
                wmma::fragment<wmma::matrix_b, 16, 16, 16, __nv_bfloat16, wmma::col_major> b_h, b_l;
                int r = (wn*32 + ni*16) * GT_PAD + ks*16;
                wmma::load_matrix_sync(b_h, sBh + r, GT_PAD);
                wmma::load_matrix_sync(b_l, sBl + r, GT_PAD);
                #pragma unroll
                for (int mi = 0; mi < 2; mi++) {
                    wmma::mma_sync(acc[mi][ni], a_h[mi], b_h, acc[mi][ni]);
                    wmma::mma_sync(acc[mi][ni], a_l[mi], b_h, acc[mi][ni]);
                    wmma::mma_sync(acc[mi][ni], a_h[mi], b_l, acc[mi][ni]);
                }
            }
        }
        __syncthreads();
    }

    if (jb.Yh == nullptr) {
        // fp32 output (qkv GEMMs)
        #pragma unroll
        for (int mi = 0; mi < 2; mi++)
            #pragma unroll
            for (int ni = 0; ni < 2; ni++) {
                long off = (long)(rowBase + wm*32 + mi*16) * HID + nBase + wn*32 + ni*16;
                wmma::store_matrix_sync(C + off, acc[mi][ni], HID, wmma::mem_row_major);
            }
    } else {
        // fused bias + bf16 hi/lo split (projection GEMM); warp-private smem roundtrip
        float* fs = (float*)smem + warp * 320;   // 16x20 fp32 tile per warp
        #pragma unroll
        for (int mi = 0; mi < 2; mi++)
            #pragma unroll
            for (int ni = 0; ni < 2; ni++) {
                wmma::store_matrix_sync(fs, acc[mi][ni], 20, wmma::mem_row_major);
                __syncwarp();
                int row0 = rowBase + wm*32 + mi*16;
                int col0 = nBase + wn*32 + ni*16;
                #pragma unroll
                for (int e = lane; e < 256; e += 32) {
                    int r = e >> 4, c = e & 15;
                    float v = fs[r*20 + c] + jb.bias[col0 + c];
                    __nv_bfloat16 h, l; bsplit(v, h, l);
                    long o = (long)(row0 + r) * HID + col0 + c;
                    jb.Yh[o] = h; jb.Yl[o] = l;
                }
                __syncwarp();
            }
    }
}

// ---------------- merged masked attention: 8 q rows/warp, pe+de in one launch ----------------
// out[b,i,h,:] = 0.5*(softmax0 @ V0 + softmax1 @ V1), row-masked. 64 q rows/CTA.
// blockIdx.x < 4: pe tiles; == 4: de. K/V/mask sources shared between jobs.
// Dynamic smem: Qs(64x68) Ks(64x68) Vs(64x68) Ps(8x8x64) mcs(64) = 68864 B.
#define AT_SMEM ((64*68*3 + 8*8*64)*4 + 64*4)
__global__ __launch_bounds__(256, 2) void attn8_kernel(
    const float* __restrict__ Qp, const float* __restrict__ Qd,
    const float* __restrict__ K0, const float* __restrict__ V0, const int* __restrict__ mc0,
    const float* __restrict__ K1, const float* __restrict__ V1, const int* __restrict__ mc1,
    const int* __restrict__ mp_, const int* __restrict__ md_,
    float* __restrict__ outP, float* __restrict__ outD)
{
    extern __shared__ float asm_f[];
    float (*Qs)[68] = (float(*)[68])asm_f;                       // 64x68
    float (*Ks)[68] = (float(*)[68])(asm_f + 64*68);             // 64x68
    float (*Vs)[68] = (float(*)[68])(asm_f + 2*64*68);           // 64x68
    float* Ps       = asm_f + 3*64*68;                           // 8 warps x 8 rows x 64
    int*   mcs      = (int*)(Ps + 8*8*64);                       // 64

    const int b = blockIdx.z, h = blockIdx.y;
    const int warp = threadIdx.x >> 5, lane = threadIdx.x & 31;

    const float* Q; float* out; const int* mrow; int Gq, qtile;
    if (blockIdx.x < 4) { Q = Qp; out = outP; mrow = mp_; Gq = GP; qtile = blockIdx.x * 64; }
    else                { Q = Qd; out = outD; mrow = md_; Gq = GD; qtile = 0; }

    const int r0 = warp * 8;
    float* Pw = Ps + warp * 512;                                  // this warp's 8x64 strip

    for (int t = threadIdx.x; t < 1024; t += 256) {
        int r = t >> 4, c4 = (t & 15) * 4;
        *(float4*)&Qs[r][c4] = *(const float4*)(Q + ((long)(b*Gq + qtile + r) * HID) + h*HD + c4);
    }
    int mr[8];
    #pragma unroll
    for (int r = 0; r < 8; r++) mr[r] = mrow[b*Gq + qtile + r0 + r];

    float res0[8], res1[8];
    #pragma unroll
    for (int r = 0; r < 8; r++) { res0[r] = 0.f; res1[r] = 0.f; }

    #pragma unroll
    for (int s = 0; s < 2; s++) {
        const float* Kc = s ? K1 : K0;
        const float* Vc = s ? V1 : V0;
        const int*   mc = s ? mc1 : mc0;
        const int    Gk = s ? GD : GP;

        float mmax[8], lsum[8], a0[8], a1[8];
        #pragma unroll
        for (int r = 0; r < 8; r++) { mmax[r] = -1e30f; lsum[r] = 0.f; a0[r] = 0.f; a1[r] = 0.f; }

        for (int j0 = 0; j0 < Gk; j0 += 64) {
            __syncthreads();
            for (int t = threadIdx.x; t < 1024; t += 256) {
                int r = t >> 4, c4 = (t & 15) * 4;
                long base = ((long)(b*Gk + j0 + r) * HID) + h*HD + c4;
                *(float4*)&Ks[r][c4] = *(const float4*)(Kc + base);
                *(float4*)&Vs[r][c4] = *(const float4*)(Vc + base);
            }
            if (threadIdx.x < 64) mcs[threadIdx.x] = mc[b*Gk + j0 + threadIdx.x];
            __syncthreads();

            float lgA[8], lgB[8];
            #pragma unroll
            for (int r = 0; r < 8; r++) { lgA[r] = 0.f; lgB[r] = 0.f; }
            #pragma unroll
            for (int d4 = 0; d4 < HD; d4 += 4) {
                float4 kA = *(const float4*)&Ks[lane][d4];
                float4 kB = *(const float4*)&Ks[lane + 32][d4];
                #pragma unroll
                for (int r = 0; r < 8; r++) {
                    float4 qv = *(const float4*)&Qs[r0 + r][d4];
                    lgA[r] += qv.x*kA.x + qv.y*kA.y + qv.z*kA.z + qv.w*kA.w;
                    lgB[r] += qv.x*kB.x + qv.y*kB.y + qv.z*kB.z + qv.w*kB.w;
                }
            }
            const int mA = mcs[lane], mB = mcs[lane + 32];
            #pragma unroll
            for (int r = 0; r < 8; r++) {
                float la = (mr[r] && mA) ? lgA[r] : lgA[r] - INFV;   // exact reference semantics
                float lb = (mr[r] && mB) ? lgB[r] : lgB[r] - INFV;
                float cm = fmaxf(la, lb);
                #pragma unroll
                for (int o = 16; o; o >>= 1) cm = fmaxf(cm, __shfl_xor_sync(0xffffffffu, cm, o));
                float mnew = fmaxf(mmax[r], cm);
                float sc   = __expf(mmax[r] - mnew);
                float pA = __expf(la - mnew);
                float pB = __expf(lb - mnew);
                Pw[r*64 + lane]      = pA;
                Pw[r*64 + lane + 32] = pB;
                float ps = pA + pB;
                #pragma unroll
                for (int o = 16; o; o >>= 1) ps += __shfl_xor_sync(0xffffffffu, ps, o);
                lsum[r] = lsum[r]*sc + ps;
                a0[r] *= sc; a1[r] *= sc;
                mmax[r] = mnew;
            }
            __syncwarp();
            #pragma unroll
            for (int jj = 0; jj < 64; jj += 4) {
                float2 v0 = *(const float2*)&Vs[jj+0][lane*2];
                float2 v1 = *(const float2*)&Vs[jj+1][lane*2];
                float2 v2 = *(const float2*)&Vs[jj+2][lane*2];
                float2 v3 = *(const float2*)&Vs[jj+3][lane*2];
                #pragma unroll
                for (int r = 0; r < 8; r++) {
                    float4 p = *(const float4*)&Pw[r*64 + jj];   // warp-uniform broadcast
                    a0[r] += p.x*v0.x + p.y*v1.x + p.z*v2.x + p.w*v3.x;
                    a1[r] += p.x*v0.y + p.y*v1.y + p.z*v2.y + p.w*v3.y;
                }
            }
            __syncwarp();
        }
        #pragma unroll
        for (int r = 0; r < 8; r++) {
            float inv = 1.f / lsum[r];
            res0[r] += a0[r] * inv;
            res1[r] += a1[r] * inv;
        }
    }

    #pragma unroll
    for (int r = 0; r < 8; r++) {
        float* op = out + ((long)(b*Gq + qtile + r0 + r) * HID) + h*HD + lane*2;
        op[0] = mr[r] ? res0[r] * 0.5f : 0.f;
        op[1] = mr[r] ? res1[r] * 0.5f : 0.f;
    }
}

// ---------------- masked mean pooling + concat ----------------
__global__ void pool_kernel(const float* __restrict__ pe, const float* __restrict__ de,
                            const int* __restrict__ mp, const int* __restrict__ md,
                            float* __restrict__ x)
{
    int b = blockIdx.x, d = threadIdx.x;
    float cp = 0.f, sp = 0.f;
    for (int g = 0; g < GP; g++) {
        float m = (float)mp[b*GP + g];
        cp += m;
        sp += m * pe[((long)b*GP + g) * HID + d];
    }
    x[b*1024 + d] = sp / cp;
    float cd = 0.f, sd = 0.f;
    for (int g = 0; g < GD; g++) {
        float m = (float)md[b*GD + g];
        cd += m;
        sd += m * de[((long)b*GD + g) * HID + d];
    }
    x[b*1024 + 512 + d] = sd / cd;
}

// ---------------- MLP layer: relu(X@W+b) then train-mode BN over batch ----------------
__global__ void mlp_layer_kernel(const float* __restrict__ X, const float* __restrict__ Wm,
                                 const float* __restrict__ bias, const float* __restrict__ gamma,
                                 const float* __restrict__ beta, float* __restrict__ Y,
                                 int Kdim, int N)
{
    int n = blockIdx.x, b = threadIdx.x;
    float s = bias[n];
    for (int k = 0; k < Kdim; k++) s += X[b*Kdim + k] * Wm[(long)k*N + n];
    s = fmaxf(s, 0.f);
    float mu = s;
    #pragma unroll
    for (int o = 16; o; o >>= 1) mu += __shfl_xor_sync(0xffffffffu, mu, o);
    mu *= (1.f/32.f);
    float diff = s - mu;
    float var = diff * diff;
    #pragma unroll
    for (int o = 16; o; o >>= 1) var += __shfl_xor_sync(0xffffffffu, var, o);
    var *= (1.f/32.f);
    Y[b*N + n] = gamma[n] * diff * rsqrtf(var + EPS) + beta[n];
}

// ---------------- final: sigmoid(x3 @ wo + bo) ----------------
__global__ void final_kernel(const float* __restrict__ X3, const float* __restrict__ wo,
                             const float* __restrict__ bo, float* __restrict__ out)
{
    int b = blockIdx.x, t = threadIdx.x;
    __shared__ float red[256];
    red[t] = X3[b*256 + t] * wo[t];
    __syncthreads();
    for (int st = 128; st; st >>= 1) {
        if (t < st) red[t] += red[t + st];
        __syncthreads();
    }
    if (t == 0) out[b] = 1.f / (1.f + __expf(-(red[0] + bo[0])));
}

// ---------------- launch ----------------
static void* sym(const void* s) { void* p = nullptr; cudaGetSymbolAddress(&p, s); return p; }

extern "C" void kernel_launch(void* const* d_in, const int* in_sizes, int n_in,
                              void* d_out, int out_size)
{
    const float* prot_embed = (const float*)d_in[0];
    const float* drug_embed = (const float*)d_in[1];
    const void*  prot_mask  = d_in[2];
    const void*  drug_mask  = d_in[3];
    const float* w_preg = (const float*)d_in[4];
    const float* b_preg = (const float*)d_in[5];
    const float* w_dreg = (const float*)d_in[6];
    const float* b_dreg = (const float*)d_in[7];
    const float* wqp = (const float*)d_in[8];
    const float* wkp = (const float*)d_in[9];
    const float* wvp = (const float*)d_in[10];
    const float* wqd = (const float*)d_in[11];
    const float* wkd = (const float*)d_in[12];
    const float* wvd = (const float*)d_in[13];
    const float* w1  = (const float*)d_in[14];
    const float* b1  = (const float*)d_in[15];
    const float* g1  = (const float*)d_in[16];
    const float* be1 = (const float*)d_in[17];
    const float* w2  = (const float*)d_in[18];
    const float* b2  = (const float*)d_in[19];
    const float* g2  = (const float*)d_in[20];
    const float* be2 = (const float*)d_in[21];
    const float* w3  = (const float*)d_in[22];
    const float* b3  = (const float*)d_in[23];
    const float* g3  = (const float*)d_in[24];
    const float* be3 = (const float*)d_in[25];
    const float* wo  = (const float*)d_in[26];
    const float* bo  = (const float*)d_in[27];

    __nv_bfloat16* pgEh = (__nv_bfloat16*)sym(d_pgEh);
    __nv_bfloat16* pgEl = (__nv_bfloat16*)sym(d_pgEl);
    __nv_bfloat16* dgEh = (__nv_bfloat16*)sym(d_dgEh);
    __nv_bfloat16* dgEl = (__nv_bfloat16*)sym(d_dgEl);
    __nv_bfloat16* pgh  = (__nv_bfloat16*)sym(d_pgh);
    __nv_bfloat16* pgl  = (__nv_bfloat16*)sym(d_pgl);
    __nv_bfloat16* dgh  = (__nv_bfloat16*)sym(d_dgh);
    __nv_bfloat16* dgl  = (__nv_bfloat16*)sym(d_dgl);
    __nv_bfloat16* wpt_h = (__nv_bfloat16*)sym(d_wpt_h);
    __nv_bfloat16* wpt_l = (__nv_bfloat16*)sym(d_wpt_l);
    __nv_bfloat16* wdt_h = (__nv_bfloat16*)sym(d_wdt_h);
    __nv_bfloat16* wdt_l = (__nv_bfloat16*)sym(d_wdt_l);
    __nv_bfloat16* wqpt  = (__nv_bfloat16*)sym(d_wqp_t);
    __nv_bfloat16* wqdt  = (__nv_bfloat16*)sym(d_wqd_t);
    float* qkvp = (float*)sym(d_qkvp);
    float* qkvd = (float*)sym(d_qkvd);
    float* qp = qkvp;  float* kp = qkvp + (long)B*GP*HID;  float* vp = qkvp + 2L*B*GP*HID;
    float* qd = qkvd;  float* kd = qkvd + (long)B*GD*HID;  float* vd = qkvd + 2L*B*GD*HID;
    float* pe  = (float*)sym(d_pe);
    float* de  = (float*)sym(d_de);
    int*   mp  = (int*)  sym(d_mp);
    int*   md  = (int*)  sym(d_md);
    float* x   = (float*)sym(d_x);
    float* x1  = (float*)sym(d_x1);
    float* x2  = (float*)sym(d_x2);
    float* x3  = (float*)sym(d_x3);
    float* out = (float*)d_out;

    cudaFuncSetAttribute(gemm_wmma_kernel, cudaFuncAttributeMaxDynamicSharedMemorySize, GT_SMEM);
    cudaFuncSetAttribute(attn8_kernel,     cudaFuncAttributeMaxDynamicSharedMemorySize, AT_SMEM);

    const long nHK = (long)HID*HID;

    // launch 0: all 8 weight transposes + splits (tiled, coalesced)
    {
        TSJobs jobs;
        jobs.j[0] = { w_preg, wpt_h, wpt_l, DP };
        jobs.j[1] = { w_dreg, wdt_h, wdt_l, DD };
        jobs.j[2] = { wqp, wqpt + 0*nHK, wqpt + 3*nHK, HID };
        jobs.j[3] = { wkp, wqpt + 1*nHK, wqpt + 4*nHK, HID };
        jobs.j[4] = { wvp, wqpt + 2*nHK, wqpt + 5*nHK, HID };
        jobs.j[5] = { wqd, wqdt + 0*nHK, wqdt + 3*nHK, HID };
        jobs.j[6] = { wkd, wqdt + 1*nHK, wqdt + 4*nHK, HID };
        jobs.j[7] = { wvd, wqdt + 2*nHK, wqdt + 5*nHK, HID };
        transpose_all_kernel<<<dim3(DP/32, HID/32, 8), dim3(32, 8)>>>(jobs);
    }

    // launches 1,2: embedding grouping + split
    {
        long tp = (long)B*GP*(DP/4);
        group_embed_split_kernel<<<(int)((tp + 255)/256), 256>>>((const float4*)prot_embed, pgEh, pgEl, LP, DP/4);
        long td = (long)B*GD*(DD/4);
        group_embed_split_kernel<<<(int)((td + 255)/256), 256>>>((const float4*)drug_embed, dgEh, dgEl, LD, DD/4);
    }

    // launch 3 (ncu capture slot): merged projection GEMM (prot + drug), fused bias+split epilogue
    {
        GJobs jobs;
        jobs.j[0] = { pgEh, pgEl, wpt_h, wpt_h, wpt_h, wpt_l, wpt_l, wpt_l,
                      nullptr, nullptr, nullptr, b_preg, pgh, pgl, DP, (B*GP)/128 };
        jobs.j[1] = { dgEh, dgEl, wdt_h, wdt_h, wdt_h, wdt_l, wdt_l, wdt_l,
                      nullptr, nullptr, nullptr, b_dreg, dgh, dgl, DD, (B*GD)/128 };
        gemm_wmma_kernel<<<dim3(8, (B*GP)/128 + (B*GD)/128, 1), 256, GT_SMEM>>>(jobs);
    }

    // launch 4: mask dtype classification (parallel)
    detect_mask_kernel<<<1, 256>>>((const unsigned char*)prot_mask);

    // launch 5: fused mask grouping
    group_mask_all_kernel<<<(B*GP + B*GD + 255)/256, 256>>>(prot_mask, drug_mask, mp, md);

    // launch 6: merged q/k/v GEMMs (prot + drug, z = q/k/v)
    {
        GJobs jobs;
        jobs.j[0] = { pgh, pgl, wqpt + 0*nHK, wqpt + 1*nHK, wqpt + 2*nHK,
                      wqpt + 3*nHK, wqpt + 4*nHK, wqpt + 5*nHK,
                      qp, kp, vp, nullptr, nullptr, nullptr, HID, (B*GP)/128 };
        jobs.j[1] = { dgh, dgl, wqdt + 0*nHK, wqdt + 1*nHK, wqdt + 2*nHK,
                      wqdt + 3*nHK, wqdt + 4*nHK, wqdt + 5*nHK,
                      qd, kd, vd, nullptr, nullptr, nullptr, HID, (B*GD)/128 };
        gemm_wmma_kernel<<<dim3(8, (B*GP)/128 + (B*GD)/128, 3), 256, GT_SMEM>>>(jobs);
    }

    // launch 7: merged cross attention (pe tiles 0..3, de tile 4)
    attn8_kernel<<<dim3(5, NH, B), 256, AT_SMEM>>>(qp, qd, kp, vp, mp, kd, vd, md, mp, md, pe, de);

    // pooling + MLP + head
    pool_kernel<<<B, 512>>>(pe, de, mp, md, x);
    mlp_layer_kernel<<<1024, 32>>>(x,  w1, b1, g1, be1, x1, 1024, 1024);
    mlp_layer_kernel<<<512,  32>>>(x1, w2, b2, g2, be2, x2, 1024, 512);
    mlp_layer_kernel<<<256,  32>>>(x2, w3, b3, g3, be3, x3, 512,  256);
    final_kernel<<<B, 256>>>(x3, wo, bo, out);

    (void)in_sizes; (void)n_in; (void)out_size;
}

// round 17
// speedup vs baseline: 1.1187x; 1.1187x over previous
#include <cuda_runtime.h>
#include <cuda_bf16.h>
#include <mma.h>
#include <math.h>
#include <stdint.h>

using namespace nvcuda;

// ---------------- problem constants ----------------
#define B   32
#define LP  2048
#define LD  512
#define DP  1280
#define DD  768
#define GP  (LP/8)      // 256
#define GD  (LD/8)      // 64
#define HID 512
#define NH  8
#define HD  64
#define INFV 1e6f
#define EPS 1e-5f

// ---------------- device scratch (static; no allocs) ----------------
__device__ __nv_bfloat16 d_pgEh[B*GP*DP], d_pgEl[B*GP*DP];
__device__ __nv_bfloat16 d_dgEh[B*GD*DD], d_dgEl[B*GD*DD];
__device__ __nv_bfloat16 d_pgh [B*GP*HID], d_pgl [B*GP*HID];
__device__ __nv_bfloat16 d_dgh [B*GD*HID], d_dgl [B*GD*HID];
__device__ __nv_bfloat16 d_wpt_h[HID*DP],  d_wpt_l[HID*DP];
__device__ __nv_bfloat16 d_wdt_h[HID*DD],  d_wdt_l[HID*DD];
__device__ __nv_bfloat16 d_wqp_t[2][3][HID*HID];
__device__ __nv_bfloat16 d_wqd_t[2][3][HID*HID];
__device__ float d_qkvp[3][B*GP*HID];
__device__ float d_qkvd[3][B*GD*HID];
__device__ float d_pe [B*GP*HID];
__device__ float d_de [B*GD*HID];
__device__ int   d_mp [B*GP];
__device__ int   d_md [B*GD];
__device__ float d_x  [B*1024];
__device__ float d_x1 [B*1024];
__device__ float d_x2 [B*512];
__device__ float d_x3 [B*256];

// ---------------- small helpers ----------------
__device__ __forceinline__ void bsplit(float x, __nv_bfloat16& h, __nv_bfloat16& l) {
    h = __float2bfloat16(x);
    l = __float2bfloat16(x - __bfloat162float(h));
}
__device__ __forceinline__ void cpa16(uint32_t daddr, const void* g) {
    asm volatile("cp.async.cg.shared.global [%0], [%1], 16;" :: "r"(daddr), "l"(g));
}
__device__ __forceinline__ int read_mask(const void* m, int idx, int layout) {
    if (layout == 0) return ((const int*)m)[idx] != 0;
    if (layout == 1) return ((const unsigned char*)m)[idx] != 0;
    return ((const float*)m)[idx] != 0.0f;
}

// ---------------- fused mask grouping with inline layout detection ----------------
// bool masks: device dtype unknown. Each block redundantly classifies the byte
// pattern of the first 4KB (random 0/1 data -> unambiguous), then groups.
//   int32:  nonzero bytes only at offset%4==0 (value 1)
//   uint8:  value-1 bytes at offsets %4 != 0
//   float32: 1.0f = 00 00 80 3F -> nonzero bytes at %4==2/3, never value 1
__global__ void group_mask_all_kernel(const void* __restrict__ mP, const void* __restrict__ mD,
                                      int* __restrict__ mp, int* __restrict__ md) {
    __shared__ int fu8, ff32;
    if (threadIdx.x == 0) { fu8 = 0; ff32 = 0; }
    __syncthreads();
    {
        const unsigned char* mb = (const unsigned char*)mP;
        int u8 = 0, f32 = 0;
        const int base = threadIdx.x * 16;
        #pragma unroll
        for (int i = base; i < base + 16; i++) {
            unsigned char v = mb[i];
            int r = i & 3;
            if (r != 0 && v != 0) { if (v == 1) u8 = 1; else f32 = 1; }
        }
        if (u8)  atomicOr(&fu8, 1);
        if (f32) atomicOr(&ff32, 1);
    }
    __syncthreads();
    const int layout = fu8 ? 1 : (ff32 ? 2 : 0);

    int idx = blockIdx.x * blockDim.x + threadIdx.x;
    if (idx < B*GP) {
        int g = idx % GP, b = idx / GP;
        int any = 0;
        #pragma unroll
        for (int r = 0; r < 8; r++) any |= read_mask(mP, b*LP + g*8 + r, layout);
        mp[idx] = any;
    } else if (idx < B*GP + B*GD) {
        int j = idx - B*GP;
        int g = j % GD, b = j / GD;
        int any = 0;
        #pragma unroll
        for (int r = 0; r < 8; r++) any |= read_mask(mD, b*LD + g*8 + r, layout);
        md[j] = any;
    }
}

// ---------------- grouping: mean over 8 rows -> bf16 hi/lo split (HBM-roof, keep) ----------------
__global__ void group_embed_split_kernel(const float4* __restrict__ X,
                                         __nv_bfloat16* __restrict__ Yh,
                                         __nv_bfloat16* __restrict__ Yl,
                                         int L, int D4) {
    long idx = (long)blockIdx.x * blockDim.x + threadIdx.x;
    long total = (long)B * (L/8) * D4;
    if (idx >= total) return;
    int d   = (int)(idx % D4);
    long bg = idx / D4;
    int g  = (int)(bg % (L/8));
    int b  = (int)(bg / (L/8));
    const float4* p = X + ((long)b*L + (long)g*8) * D4 + d;
    float sx=0.f, sy=0.f, sz=0.f, sw=0.f;
    #pragma unroll
    for (int r = 0; r < 8; r++) {
        float4 v = p[(long)r*D4];
        sx += v.x; sy += v.y; sz += v.z; sw += v.w;
    }
    __nv_bfloat16 h0,l0,h1,l1,h2,l2,h3,l3;
    bsplit(sx*0.125f, h0, l0); bsplit(sy*0.125f, h1, l1);
    bsplit(sz*0.125f, h2, l2); bsplit(sw*0.125f, h3, l3);
    __nv_bfloat162* yh = (__nv_bfloat162*)Yh;
    __nv_bfloat162* yl = (__nv_bfloat162*)Yl;
    yh[idx*2+0] = __nv_bfloat162(h0, h1); yh[idx*2+1] = __nv_bfloat162(h2, h3);
    yl[idx*2+0] = __nv_bfloat162(l0, l1); yl[idx*2+1] = __nv_bfloat162(l2, l3);
}

// ---------------- smem-tiled weight transpose + bf16 split (8 jobs, one launch) ----------------
struct TSJob  { const float* W; __nv_bfloat16 *Th, *Tl; int K; };
struct TSJobs { TSJob j[8]; };
__global__ void transpose_all_kernel(TSJobs jobs) {
    TSJob jb = jobs.j[blockIdx.z];
    int k0 = blockIdx.x * 32, n0 = blockIdx.y * 32;
    if (k0 >= jb.K) return;
    __shared__ __nv_bfloat16 th[32][33], tl[32][33];
    int tx = threadIdx.x, ty = threadIdx.y;   // (32, 8)
    #pragma unroll
    for (int i = 0; i < 4; i++) {
        int kk = ty + i*8;
        float v = jb.W[(long)(k0 + kk) * HID + n0 + tx];   // coalesced (n fast)
        bsplit(v, th[kk][tx], tl[kk][tx]);
    }
    __syncthreads();
    #pragma unroll
    for (int i = 0; i < 4; i++) {
        int nn = ty + i*8;
        long o = (long)(n0 + nn) * jb.K + k0 + tx;          // coalesced (k fast)
        jb.Th[o] = th[tx][nn];
        jb.Tl[o] = tl[tx][nn];
    }
}

// ---------------- wmma GEMM (R15 measured-best config): 128x128, 2 CTAs/SM ----------------
// C[M,512] = A[M,K] @ T[512,K]^T ; compensated bf16: Ah*Bh + Al*Bh + Ah*Bl.
// 8 warps: warp tile 32x64 (2x4 frags); K in 32-chunks, cp.async double-buffered.
// R16 lesson: 128x64 tile raised frag-load/MMA ratio (0.5 -> 0.67) and doubled
// A-traffic — occupancy gain did not pay for it. This is the 135.5us/45.9%-tensor shape.
#define GT_PAD 40
#define GT_ARR (128*GT_PAD)
#define GT_BUF (4*GT_ARR)
#define GT_SMEM (2*GT_BUF*2)
struct GJob {
    const __nv_bfloat16 *Ah, *Al;
    const __nv_bfloat16 *Wh0, *Wh1, *Wh2, *Wl0, *Wl1, *Wl2;
    float *C0, *C1, *C2;
    const float* bias;
    __nv_bfloat16 *Yh, *Yl;
    int K, tiles;
};
struct GJobs { GJob j[2]; };
__global__ __launch_bounds__(256, 2) void gemm_wmma_kernel(GJobs jobs) {
    extern __shared__ __nv_bfloat16 smem[];
    int yt = blockIdx.y;
    GJob jb = jobs.j[0];
    if (yt >= jb.tiles) { yt -= jb.tiles; jb = jobs.j[1]; }

    const __nv_bfloat16* Wh = (blockIdx.z == 0) ? jb.Wh0 : (blockIdx.z == 1) ? jb.Wh1 : jb.Wh2;
    const __nv_bfloat16* Wl = (blockIdx.z == 0) ? jb.Wl0 : (blockIdx.z == 1) ? jb.Wl1 : jb.Wl2;
    float* C                = (blockIdx.z == 0) ? jb.C0  : (blockIdx.z == 1) ? jb.C1  : jb.C2;
    const __nv_bfloat16* Ahi = jb.Ah;
    const __nv_bfloat16* Alo = jb.Al;
    const int K = jb.K;

    const int tid  = threadIdx.x;
    const int warp = tid >> 5;
    const int lane = tid & 31;
    const int wm   = warp & 3;
    const int wn   = warp >> 2;
    const int rowBase = yt * 128, nBase = blockIdx.x * 128;
    const int nCh = K >> 5;

    wmma::fragment<wmma::accumulator, 16, 16, 16, float> acc[2][4];
    #pragma unroll
    for (int mi = 0; mi < 2; mi++)
        #pragma unroll
        for (int ni = 0; ni < 4; ni++) wmma::fill_fragment(acc[mi][ni], 0.f);

    auto stage = [&](int ch, int buf) {
        const int k0 = ch << 5;
        __nv_bfloat16* s = smem + buf * GT_BUF;
        for (int u = tid; u < 512; u += 256) {
            int r = u >> 2, c8 = (u & 3) << 3;
            long ga = (long)(rowBase + r) * K + k0 + c8;
            long gb = (long)(nBase   + r) * K + k0 + c8;
            uint32_t d0 = (uint32_t)__cvta_generic_to_shared(s + r*GT_PAD + c8);
            cpa16(d0,            Ahi + ga);
            cpa16(d0 + 2*GT_ARR, Alo + ga);
            cpa16(d0 + 4*GT_ARR, Wh  + gb);
            cpa16(d0 + 6*GT_ARR, Wl  + gb);
        }
    };

    stage(0, 0);
    asm volatile("cp.async.commit_group;" ::: "memory");

    for (int ch = 0; ch < nCh; ch++) {
        const int buf = ch & 1;
        if (ch + 1 < nCh) {
            stage(ch + 1, 1 - buf);
            asm volatile("cp.async.commit_group;" ::: "memory");
            asm volatile("cp.async.wait_group 1;" ::: "memory");
        } else {
            asm volatile("cp.async.wait_group 0;" ::: "memory");
        }
        __syncthreads();

        const __nv_bfloat16* sAh = smem + buf*GT_BUF;
        const __nv_bfloat16* sAl = sAh + GT_ARR;
        const __nv_bfloat16* sBh = sAh + 2*GT_ARR;
        const __nv_bfloat16* sBl = sAh + 3*GT_ARR;

        #pragma unroll
        for (int ks = 0; ks < 2; ks++) {
            wmma::fragment<wmma::matrix_a, 16, 16, 16, __nv_bfloat16, wmma::row_major> a_h[2], a_l[2];
            #pragma unroll
            for (int mi = 0; mi < 2; mi++) {
                int r = (wm*32 + mi*16) * GT_PAD + ks*16;
                wmma::load_matrix_sync(a_h[mi], sAh + r, GT_PAD);
                wmma::load_matrix_sync(a_l[mi], sAl + r, GT_PAD);
            }
            #pragma unroll
            for (int ni = 0; ni < 4; ni++) {
                wmma::fragment<wmma::matrix_b, 16, 16, 16, __nv_bfloat16, wmma::col_major> b_h, b_l;
                int r = (wn*64 + ni*16) * GT_PAD + ks*16;
                wmma::load_matrix_sync(b_h, sBh + r, GT_PAD);
                wmma::load_matrix_sync(b_l, sBl + r, GT_PAD);
                #pragma unroll
                for (int mi = 0; mi < 2; mi++) {
                    wmma::mma_sync(acc[mi][ni], a_h[mi], b_h, acc[mi][ni]);
                    wmma::mma_sync(acc[mi][ni], a_l[mi], b_h, acc[mi][ni]);
                    wmma::mma_sync(acc[mi][ni], a_h[mi], b_l, acc[mi][ni]);
                }
            }
        }
        __syncthreads();
    }

    if (jb.Yh == nullptr) {
        // fp32 output (qkv GEMMs)
        #pragma unroll
        for (int mi = 0; mi < 2; mi++)
            #pragma unroll
            for (int ni = 0; ni < 4; ni++) {
                long off = (long)(rowBase + wm*32 + mi*16) * HID + nBase + wn*64 + ni*16;
                wmma::store_matrix_sync(C + off, acc[mi][ni], HID, wmma::mem_row_major);
            }
    } else {
        // fused bias + bf16 hi/lo split (projection GEMM); warp-private smem roundtrip
        float* fs = (float*)smem + warp * 320;   // 16x20 fp32 tile per warp
        #pragma unroll
        for (int mi = 0; mi < 2; mi++)
            #pragma unroll
            for (int ni = 0; ni < 4; ni++) {
                wmma::store_matrix_sync(fs, acc[mi][ni], 20, wmma::mem_row_major);
                __syncwarp();
                int row0 = rowBase + wm*32 + mi*16;
                int col0 = nBase + wn*64 + ni*16;
                #pragma unroll
                for (int e = lane; e < 256; e += 32) {
                    int r = e >> 4, c = e & 15;
                    float v = fs[r*20 + c] + jb.bias[col0 + c];
                    __nv_bfloat16 h, l; bsplit(v, h, l);
                    long o = (long)(row0 + r) * HID + col0 + c;
                    jb.Yh[o] = h; jb.Yl[o] = l;
                }
                __syncwarp();
            }
    }
}

// ---------------- merged masked attention: 8 q rows/warp, pe+de in one launch ----------------
// out[b,i,h,:] = 0.5*(softmax0 @ V0 + softmax1 @ V1), row-masked. 64 q rows/CTA.
// blockIdx.x < 4: pe tiles; == 4: de. K/V/mask sources shared between jobs.
// Dynamic smem: Qs(64x68) Ks(64x68) Vs(64x68) Ps(8x8x64) mcs(64) = 68864 B.
#define AT_SMEM ((64*68*3 + 8*8*64)*4 + 64*4)
__global__ __launch_bounds__(256, 2) void attn8_kernel(
    const float* __restrict__ Qp, const float* __restrict__ Qd,
    const float* __restrict__ K0, const float* __restrict__ V0, const int* __restrict__ mc0,
    const float* __restrict__ K1, const float* __restrict__ V1, const int* __restrict__ mc1,
    const int* __restrict__ mp_, const int* __restrict__ md_,
    float* __restrict__ outP, float* __restrict__ outD)
{
    extern __shared__ float asm_f[];
    float (*Qs)[68] = (float(*)[68])asm_f;                       // 64x68
    float (*Ks)[68] = (float(*)[68])(asm_f + 64*68);             // 64x68
    float (*Vs)[68] = (float(*)[68])(asm_f + 2*64*68);           // 64x68
    float* Ps       = asm_f + 3*64*68;                           // 8 warps x 8 rows x 64
    int*   mcs      = (int*)(Ps + 8*8*64);                       // 64

    const int b = blockIdx.z, h = blockIdx.y;
    const int warp = threadIdx.x >> 5, lane = threadIdx.x & 31;

    const float* Q; float* out; const int* mrow; int Gq, qtile;
    if (blockIdx.x < 4) { Q = Qp; out = outP; mrow = mp_; Gq = GP; qtile = blockIdx.x * 64; }
    else                { Q = Qd; out = outD; mrow = md_; Gq = GD; qtile = 0; }

    const int r0 = warp * 8;
    float* Pw = Ps + warp * 512;                                  // this warp's 8x64 strip

    for (int t = threadIdx.x; t < 1024; t += 256) {
        int r = t >> 4, c4 = (t & 15) * 4;
        *(float4*)&Qs[r][c4] = *(const float4*)(Q + ((long)(b*Gq + qtile + r) * HID) + h*HD + c4);
    }
    int mr[8];
    #pragma unroll
    for (int r = 0; r < 8; r++) mr[r] = mrow[b*Gq + qtile + r0 + r];

    float res0[8], res1[8];
    #pragma unroll
    for (int r = 0; r < 8; r++) { res0[r] = 0.f; res1[r] = 0.f; }

    #pragma unroll
    for (int s = 0; s < 2; s++) {
        const float* Kc = s ? K1 : K0;
        const float* Vc = s ? V1 : V0;
        const int*   mc = s ? mc1 : mc0;
        const int    Gk = s ? GD : GP;

        float mmax[8], lsum[8], a0[8], a1[8];
        #pragma unroll
        for (int r = 0; r < 8; r++) { mmax[r] = -1e30f; lsum[r] = 0.f; a0[r] = 0.f; a1[r] = 0.f; }

        for (int j0 = 0; j0 < Gk; j0 += 64) {
            __syncthreads();
            for (int t = threadIdx.x; t < 1024; t += 256) {
                int r = t >> 4, c4 = (t & 15) * 4;
                long base = ((long)(b*Gk + j0 + r) * HID) + h*HD + c4;
                *(float4*)&Ks[r][c4] = *(const float4*)(Kc + base);
                *(float4*)&Vs[r][c4] = *(const float4*)(Vc + base);
            }
            if (threadIdx.x < 64) mcs[threadIdx.x] = mc[b*Gk + j0 + threadIdx.x];
            __syncthreads();

            float lgA[8], lgB[8];
            #pragma unroll
            for (int r = 0; r < 8; r++) { lgA[r] = 0.f; lgB[r] = 0.f; }
            #pragma unroll
            for (int d4 = 0; d4 < HD; d4 += 4) {
                float4 kA = *(const float4*)&Ks[lane][d4];
                float4 kB = *(const float4*)&Ks[lane + 32][d4];
                #pragma unroll
                for (int r = 0; r < 8; r++) {
                    float4 qv = *(const float4*)&Qs[r0 + r][d4];
                    lgA[r] += qv.x*kA.x + qv.y*kA.y + qv.z*kA.z + qv.w*kA.w;
                    lgB[r] += qv.x*kB.x + qv.y*kB.y + qv.z*kB.z + qv.w*kB.w;
                }
            }
            const int mA = mcs[lane], mB = mcs[lane + 32];
            #pragma unroll
            for (int r = 0; r < 8; r++) {
                float la = (mr[r] && mA) ? lgA[r] : lgA[r] - INFV;   // exact reference semantics
                float lb = (mr[r] && mB) ? lgB[r] : lgB[r] - INFV;
                float cm = fmaxf(la, lb);
                #pragma unroll
                for (int o = 16; o; o >>= 1) cm = fmaxf(cm, __shfl_xor_sync(0xffffffffu, cm, o));
                float mnew = fmaxf(mmax[r], cm);
                float sc   = __expf(mmax[r] - mnew);
                float pA = __expf(la - mnew);
                float pB = __expf(lb - mnew);
                Pw[r*64 + lane]      = pA;
                Pw[r*64 + lane + 32] = pB;
                float ps = pA + pB;
                #pragma unroll
                for (int o = 16; o; o >>= 1) ps += __shfl_xor_sync(0xffffffffu, ps, o);
                lsum[r] = lsum[r]*sc + ps;
                a0[r] *= sc; a1[r] *= sc;
                mmax[r] = mnew;
            }
            __syncwarp();
            #pragma unroll
            for (int jj = 0; jj < 64; jj += 4) {
                float2 v0 = *(const float2*)&Vs[jj+0][lane*2];
                float2 v1 = *(const float2*)&Vs[jj+1][lane*2];
                float2 v2 = *(const float2*)&Vs[jj+2][lane*2];
                float2 v3 = *(const float2*)&Vs[jj+3][lane*2];
                #pragma unroll
                for (int r = 0; r < 8; r++) {
                    float4 p = *(const float4*)&Pw[r*64 + jj];   // warp-uniform broadcast
                    a0[r] += p.x*v0.x + p.y*v1.x + p.z*v2.x + p.w*v3.x;
                    a1[r] += p.x*v0.y + p.y*v1.y + p.z*v2.y + p.w*v3.y;
                }
            }
            __syncwarp();
        }
        #pragma unroll
        for (int r = 0; r < 8; r++) {
            float inv = 1.f / lsum[r];
            res0[r] += a0[r] * inv;
            res1[r] += a1[r] * inv;
        }
    }

    #pragma unroll
    for (int r = 0; r < 8; r++) {
        float* op = out + ((long)(b*Gq + qtile + r0 + r) * HID) + h*HD + lane*2;
        op[0] = mr[r] ? res0[r] * 0.5f : 0.f;
        op[1] = mr[r] ? res1[r] * 0.5f : 0.f;
    }
}

// ---------------- masked mean pooling + concat ----------------
__global__ void pool_kernel(const float* __restrict__ pe, const float* __restrict__ de,
                            const int* __restrict__ mp, const int* __restrict__ md,
                            float* __restrict__ x)
{
    int b = blockIdx.x, d = threadIdx.x;
    float cp = 0.f, sp = 0.f;
    for (int g = 0; g < GP; g++) {
        float m = (float)mp[b*GP + g];
        cp += m;
        sp += m * pe[((long)b*GP + g) * HID + d];
    }
    x[b*1024 + d] = sp / cp;
    float cd = 0.f, sd = 0.f;
    for (int g = 0; g < GD; g++) {
        float m = (float)md[b*GD + g];
        cd += m;
        sd += m * de[((long)b*GD + g) * HID + d];
    }
    x[b*1024 + 512 + d] = sd / cd;
}

// ---------------- MLP layer: relu(X@W+b) then train-mode BN over batch ----------------
// X rows read as float4 (K % 4 == 0 for 1024/1024/512); W broadcast loads unchanged.
__global__ void mlp_layer_kernel(const float* __restrict__ X, const float* __restrict__ Wm,
                                 const float* __restrict__ bias, const float* __restrict__ gamma,
                                 const float* __restrict__ beta, float* __restrict__ Y,
                                 int Kdim, int N)
{
    int n = blockIdx.x, b = threadIdx.x;
    const float4* x4 = (const float4*)(X + b*Kdim);
    float s = bias[n];
    for (int k4 = 0; k4 < (Kdim >> 2); k4++) {
        float4 xv = x4[k4];
        int k = k4 << 2;
        s += xv.x * Wm[(long)(k+0)*N + n];
        s += xv.y * Wm[(long)(k+1)*N + n];
        s += xv.z * Wm[(long)(k+2)*N + n];
        s += xv.w * Wm[(long)(k+3)*N + n];
    }
    s = fmaxf(s, 0.f);
    float mu = s;
    #pragma unroll
    for (int o = 16; o; o >>= 1) mu += __shfl_xor_sync(0xffffffffu, mu, o);
    mu *= (1.f/32.f);
    float diff = s - mu;
    float var = diff * diff;
    #pragma unroll
    for (int o = 16; o; o >>= 1) var += __shfl_xor_sync(0xffffffffu, var, o);
    var *= (1.f/32.f);
    Y[b*N + n] = gamma[n] * diff * rsqrtf(var + EPS) + beta[n];
}

// ---------------- final: sigmoid(x3 @ wo + bo) ----------------
__global__ void final_kernel(const float* __restrict__ X3, const float* __restrict__ wo,
                             const float* __restrict__ bo, float* __restrict__ out)
{
    int b = blockIdx.x, t = threadIdx.x;
    __shared__ float red[256];
    red[t] = X3[b*256 + t] * wo[t];
    __syncthreads();
    for (int st = 128; st; st >>= 1) {
        if (t < st) red[t] += red[t + st];
        __syncthreads();
    }
    if (t == 0) out[b] = 1.f / (1.f + __expf(-(red[0] + bo[0])));
}

// ---------------- launch ----------------
static void* sym(const void* s) { void* p = nullptr; cudaGetSymbolAddress(&p, s); return p; }

extern "C" void kernel_launch(void* const* d_in, const int* in_sizes, int n_in,
                              void* d_out, int out_size)
{
    const float* prot_embed = (const float*)d_in[0];
    const float* drug_embed = (const float*)d_in[1];
    const void*  prot_mask  = d_in[2];
    const void*  drug_mask  = d_in[3];
    const float* w_preg = (const float*)d_in[4];
    const float* b_preg = (const float*)d_in[5];
    const float* w_dreg = (const float*)d_in[6];
    const float* b_dreg = (const float*)d_in[7];
    const float* wqp = (const float*)d_in[8];
    const float* wkp = (const float*)d_in[9];
    const float* wvp = (const float*)d_in[10];
    const float* wqd = (const float*)d_in[11];
    const float* wkd = (const float*)d_in[12];
    const float* wvd = (const float*)d_in[13];
    const float* w1  = (const float*)d_in[14];
    const float* b1  = (const float*)d_in[15];
    const float* g1  = (const float*)d_in[16];
    const float* be1 = (const float*)d_in[17];
    const float* w2  = (const float*)d_in[18];
    const float* b2  = (const float*)d_in[19];
    const float* g2  = (const float*)d_in[20];
    const float* be2 = (const float*)d_in[21];
    const float* w3  = (const float*)d_in[22];
    const float* b3  = (const float*)d_in[23];
    const float* g3  = (const float*)d_in[24];
    const float* be3 = (const float*)d_in[25];
    const float* wo  = (const float*)d_in[26];
    const float* bo  = (const float*)d_in[27];

    __nv_bfloat16* pgEh = (__nv_bfloat16*)sym(d_pgEh);
    __nv_bfloat16* pgEl = (__nv_bfloat16*)sym(d_pgEl);
    __nv_bfloat16* dgEh = (__nv_bfloat16*)sym(d_dgEh);
    __nv_bfloat16* dgEl = (__nv_bfloat16*)sym(d_dgEl);
    __nv_bfloat16* pgh  = (__nv_bfloat16*)sym(d_pgh);
    __nv_bfloat16* pgl  = (__nv_bfloat16*)sym(d_pgl);
    __nv_bfloat16* dgh  = (__nv_bfloat16*)sym(d_dgh);
    __nv_bfloat16* dgl  = (__nv_bfloat16*)sym(d_dgl);
    __nv_bfloat16* wpt_h = (__nv_bfloat16*)sym(d_wpt_h);
    __nv_bfloat16* wpt_l = (__nv_bfloat16*)sym(d_wpt_l);
    __nv_bfloat16* wdt_h = (__nv_bfloat16*)sym(d_wdt_h);
    __nv_bfloat16* wdt_l = (__nv_bfloat16*)sym(d_wdt_l);
    __nv_bfloat16* wqpt  = (__nv_bfloat16*)sym(d_wqp_t);
    __nv_bfloat16* wqdt  = (__nv_bfloat16*)sym(d_wqd_t);
    float* qkvp = (float*)sym(d_qkvp);
    float* qkvd = (float*)sym(d_qkvd);
    float* qp = qkvp;  float* kp = qkvp + (long)B*GP*HID;  float* vp = qkvp + 2L*B*GP*HID;
    float* qd = qkvd;  float* kd = qkvd + (long)B*GD*HID;  float* vd = qkvd + 2L*B*GD*HID;
    float* pe  = (float*)sym(d_pe);
    float* de  = (float*)sym(d_de);
    int*   mp  = (int*)  sym(d_mp);
    int*   md  = (int*)  sym(d_md);
    float* x   = (float*)sym(d_x);
    float* x1  = (float*)sym(d_x1);
    float* x2  = (float*)sym(d_x2);
    float* x3  = (float*)sym(d_x3);
    float* out = (float*)d_out;

    cudaFuncSetAttribute(gemm_wmma_kernel, cudaFuncAttributeMaxDynamicSharedMemorySize, GT_SMEM);
    cudaFuncSetAttribute(attn8_kernel,     cudaFuncAttributeMaxDynamicSharedMemorySize, AT_SMEM);

    const long nHK = (long)HID*HID;

    // launch 0: all 8 weight transposes + splits (tiled, coalesced)
    {
        TSJobs jobs;
        jobs.j[0] = { w_preg, wpt_h, wpt_l, DP };
        jobs.j[1] = { w_dreg, wdt_h, wdt_l, DD };
        jobs.j[2] = { wqp, wqpt + 0*nHK, wqpt + 3*nHK, HID };
        jobs.j[3] = { wkp, wqpt + 1*nHK, wqpt + 4*nHK, HID };
        jobs.j[4] = { wvp, wqpt + 2*nHK, wqpt + 5*nHK, HID };
        jobs.j[5] = { wqd, wqdt + 0*nHK, wqdt + 3*nHK, HID };
        jobs.j[6] = { wkd, wqdt + 1*nHK, wqdt + 4*nHK, HID };
        jobs.j[7] = { wvd, wqdt + 2*nHK, wqdt + 5*nHK, HID };
        transpose_all_kernel<<<dim3(DP/32, HID/32, 8), dim3(32, 8)>>>(jobs);
    }

    // launches 1,2: embedding grouping + split
    {
        long tp = (long)B*GP*(DP/4);
        group_embed_split_kernel<<<(int)((tp + 255)/256), 256>>>((const float4*)prot_embed, pgEh, pgEl, LP, DP/4);
        long td = (long)B*GD*(DD/4);
        group_embed_split_kernel<<<(int)((td + 255)/256), 256>>>((const float4*)drug_embed, dgEh, dgEl, LD, DD/4);
    }

    // launch 3 (ncu capture slot): merged projection GEMM (prot + drug), fused bias+split epilogue
    {
        GJobs jobs;
        jobs.j[0] = { pgEh, pgEl, wpt_h, wpt_h, wpt_h, wpt_l, wpt_l, wpt_l,
                      nullptr, nullptr, nullptr, b_preg, pgh, pgl, DP, (B*GP)/128 };
        jobs.j[1] = { dgEh, dgEl, wdt_h, wdt_h, wdt_h, wdt_l, wdt_l, wdt_l,
                      nullptr, nullptr, nullptr, b_dreg, dgh, dgl, DD, (B*GD)/128 };
        gemm_wmma_kernel<<<dim3(4, (B*GP)/128 + (B*GD)/128, 1), 256, GT_SMEM>>>(jobs);
    }

    // launch 4: fused mask-layout detection + mask grouping
    group_mask_all_kernel<<<(B*GP + B*GD + 255)/256, 256>>>(prot_mask, drug_mask, mp, md);

    // launch 5: merged q/k/v GEMMs (prot + drug, z = q/k/v)
    {
        GJobs jobs;
        jobs.j[0] = { pgh, pgl, wqpt + 0*nHK, wqpt + 1*nHK, wqpt + 2*nHK,
                      wqpt + 3*nHK, wqpt + 4*nHK, wqpt + 5*nHK,
                      qp, kp, vp, nullptr, nullptr, nullptr, HID, (B*GP)/128 };
        jobs.j[1] = { dgh, dgl, wqdt + 0*nHK, wqdt + 1*nHK, wqdt + 2*nHK,
                      wqdt + 3*nHK, wqdt + 4*nHK, wqdt + 5*nHK,
                      qd, kd, vd, nullptr, nullptr, nullptr, HID, (B*GD)/128 };
        gemm_wmma_kernel<<<dim3(4, (B*GP)/128 + (B*GD)/128, 3), 256, GT_SMEM>>>(jobs);
    }

    // launch 6: merged cross attention (pe tiles 0..3, de tile 4)
    attn8_kernel<<<dim3(5, NH, B), 256, AT_SMEM>>>(qp, qd, kp, vp, mp, kd, vd, md, mp, md, pe, de);

    // pooling + MLP + head
    pool_kernel<<<B, 512>>>(pe, de, mp, md, x);
    mlp_layer_kernel<<<1024, 32>>>(x,  w1, b1, g1, be1, x1, 1024, 1024);
    mlp_layer_kernel<<<512,  32>>>(x1, w2, b2, g2, be2, x2, 1024, 512);
    mlp_layer_kernel<<<256,  32>>>(x2, w3, b3, g3, be3, x3, 512,  256);
    final_kernel<<<B, 256>>>(x3, wo, bo, out);

    (void)in_sizes; (void)n_in; (void)out_size;
}